// round 4
// baseline (speedup 1.0000x reference)
#include <cuda_runtime.h>
#include <cstdint>

#define BB   64
#define MH   64
#define MW   32
#define DD   512
#define SS   8
#define HIDN 64

typedef unsigned long long ull;

// ---------------- f32x2 packed helpers (Blackwell FFMA2 via PTX) -----------
__device__ __forceinline__ ull dup2(float x) {
    ull r; asm("mov.b64 %0, {%1, %1};" : "=l"(r) : "f"(x)); return r;
}
__device__ __forceinline__ void fma2(ull &a, ull x, ull y) {
    asm("fma.rn.f32x2 %0, %1, %2, %0;" : "+l"(a) : "l"(x), "l"(y));
}
__device__ __forceinline__ float2 unpack2(ull v) {
    float2 f; asm("mov.b64 {%0, %1}, %2;" : "=f"(f.x), "=f"(f.y) : "l"(v)); return f;
}
// streaming 128-bit store (evict-first: output is write-once)
__device__ __forceinline__ void stcs4(float* p, float4 v) {
    asm volatile("st.global.cs.v4.f32 [%0], {%1,%2,%3,%4};"
                 :: "l"(p), "f"(v.x), "f"(v.y), "f"(v.z), "f"(v.w) : "memory");
}

// ---------------------------------------------------------------------------
// Fused kernel, one (b, y) row per block, 256 threads.
//   h = gelu(coords @ w1 + b1) -> smem (pre-duplicated as f32x2)
//   delta = h @ w2 : M=32(x) N=512(d) K=64, thread tile 8x*8d, f32x2 over d.
//   w2 read directly from global (L1-resident, 128 KB).
//   out = mask ? bilinear(canon) + delta + b2 : 0 ; mask plane appended.
// Invalid rows: pure zero-store. Warps with x-chunk >= Ws skip the GEMM.
// Smem: a_s (64*32 ull, 16 KB) + cy (8*512 f32, 16 KB) = 32 KB -> 2 CTAs/SM.
// ---------------------------------------------------------------------------
__global__ void __launch_bounds__(256, 2)
k_main(const float* __restrict__ canon, const float* __restrict__ w1,
       const float* __restrict__ b1, const float* __restrict__ w2g,
       const float* __restrict__ b2, const int* __restrict__ hl,
       const int* __restrict__ wl, float* __restrict__ out, int write_mask)
{
    __shared__ __align__(16) ull   a_s[HIDN * MW];   // 16 KB, h dup'd
    __shared__ __align__(16) float cy_s[SS * DD];    // 16 KB, y-lerped canon

    const int b   = blockIdx.y;
    const int y   = blockIdx.x;
    const int tid = threadIdx.x;

    const int Hs = min(max(hl[b], 1), MH);
    const int Ws = min(max(wl[b], 1), MW);
    const float invH = (Hs > 1) ? 1.f / (float)(Hs - 1) : 0.f;
    const float invW = (Ws > 1) ? 1.f / (float)(Ws - 1) : 0.f;

    float* orow = out + (size_t)(b * MH + y) * MW * DD;
    float* mrow = out + (size_t)BB * MH * MW * DD + (b * MH + y) * MW;

    if (y >= Hs) {            // invalid row: pure zero-store fast path
        float4 z = make_float4(0.f, 0.f, 0.f, 0.f);
        #pragma unroll
        for (int i = 0; i < 16; i++)              // 4096 float4
            stcs4(&orow[(tid + i * 256) * 4], z);
        if (write_mask && tid < MW) mrow[tid] = 0.f;
        return;
    }

    const float u = (float)y * invH;

    // ---- h = gelu(u*w1a + v*w1b + b1), duplicated f32x2, into a_s[k][x] ----
    {
        const int gx  = tid & 31;
        const int gk0 = (tid >> 5) * 8;
        const float gv = (float)gx * invW;
        #pragma unroll
        for (int j = 0; j < 8; j++) {
            int k = gk0 + j;
            float pre = fmaf(u, __ldg(&w1[k]),
                             fmaf(gv, __ldg(&w1[HIDN + k]), __ldg(&b1[k])));
            float h = 0.5f * pre * (1.f + erff(pre * 0.70710678118654752f));
            a_s[k * MW + gx] = dup2(h);
        }
    }

    // ---- cy: y-lerped canonical rows [8][512] ----
    {
        float sy = fminf(u * (float)(SS - 1), (float)(SS - 1));
        int   yy0 = (int)sy;
        int   yy1 = min(yy0 + 1, SS - 1);
        float wy  = sy - (float)yy0;
        #pragma unroll
        for (int i = 0; i < 4; i++) {
            int lin = tid + i * 256;               // 1024 float4
            int xx  = lin >> 7;
            int off = (lin & 127) * 4;
            float4 c0 = *(const float4*)&canon[(yy0 * SS + xx) * DD + off];
            float4 c1 = *(const float4*)&canon[(yy1 * SS + xx) * DD + off];
            float4 r;
            r.x = fmaf(wy, c1.x - c0.x, c0.x);
            r.y = fmaf(wy, c1.y - c0.y, c0.y);
            r.z = fmaf(wy, c1.z - c0.z, c0.z);
            r.w = fmaf(wy, c1.w - c0.w, c0.w);
            *(float4*)&cy_s[xx * DD + off] = r;
        }
    }
    __syncthreads();

    const int tn  = tid & 63;        // d group: d = tn*8 .. +7
    const int tm  = tid >> 6;        // warp-uniform x group
    const int x0b = tm * 8;

    ull acc[8][4];
    #pragma unroll
    for (int m = 0; m < 8; m++)
        #pragma unroll
        for (int p = 0; p < 4; p++) acc[m][p] = 0ULL;

    if (x0b < Ws) {                  // warp-uniform skip of masked x-chunks
        const float* wbase = w2g + tn * 8;
        #pragma unroll 4
        for (int k = 0; k < HIDN; k++) {
            const ull* ak = &a_s[k * MW + x0b];
            ulonglong2 a01 = *(const ulonglong2*)(ak);       // LDS.128 bcast
            ulonglong2 a23 = *(const ulonglong2*)(ak + 2);
            ulonglong2 a45 = *(const ulonglong2*)(ak + 4);
            ulonglong2 a67 = *(const ulonglong2*)(ak + 6);
            const float* wrow = wbase + k * DD;
            ulonglong2 b01 = *(const ulonglong2*)(wrow);     // LDG.128 L1-hit
            ulonglong2 b23 = *(const ulonglong2*)(wrow + 4);
            fma2(acc[0][0], a01.x, b01.x); fma2(acc[0][1], a01.x, b01.y);
            fma2(acc[0][2], a01.x, b23.x); fma2(acc[0][3], a01.x, b23.y);
            fma2(acc[1][0], a01.y, b01.x); fma2(acc[1][1], a01.y, b01.y);
            fma2(acc[1][2], a01.y, b23.x); fma2(acc[1][3], a01.y, b23.y);
            fma2(acc[2][0], a23.x, b01.x); fma2(acc[2][1], a23.x, b01.y);
            fma2(acc[2][2], a23.x, b23.x); fma2(acc[2][3], a23.x, b23.y);
            fma2(acc[3][0], a23.y, b01.x); fma2(acc[3][1], a23.y, b01.y);
            fma2(acc[3][2], a23.y, b23.x); fma2(acc[3][3], a23.y, b23.y);
            fma2(acc[4][0], a45.x, b01.x); fma2(acc[4][1], a45.x, b01.y);
            fma2(acc[4][2], a45.x, b23.x); fma2(acc[4][3], a45.x, b23.y);
            fma2(acc[5][0], a45.y, b01.x); fma2(acc[5][1], a45.y, b01.y);
            fma2(acc[5][2], a45.y, b23.x); fma2(acc[5][3], a45.y, b23.y);
            fma2(acc[6][0], a67.x, b01.x); fma2(acc[6][1], a67.x, b01.y);
            fma2(acc[6][2], a67.x, b23.x); fma2(acc[6][3], a67.x, b23.y);
            fma2(acc[7][0], a67.y, b01.x); fma2(acc[7][1], a67.y, b01.y);
            fma2(acc[7][2], a67.y, b23.x); fma2(acc[7][3], a67.y, b23.y);
        }
    }

    // ---- epilogue: + b2 + bilinear-x, mask, vectorized streaming store ----
    const float4 b2a = *(const float4*)&b2[tn * 8];
    const float4 b2b = *(const float4*)&b2[tn * 8 + 4];
    #pragma unroll
    for (int m = 0; m < 8; m++) {
        int x = x0b + m;
        float4 oa = make_float4(0.f, 0.f, 0.f, 0.f);
        float4 ob = make_float4(0.f, 0.f, 0.f, 0.f);
        if (x < Ws) {
            float sx = fminf((float)x * invW * (float)(SS - 1), (float)(SS - 1));
            int   xx0 = (int)sx;
            int   xx1 = min(xx0 + 1, SS - 1);
            float wx = sx - (float)xx0;
            float4 ca0 = *(float4*)&cy_s[xx0 * DD + tn * 8];
            float4 ca1 = *(float4*)&cy_s[xx1 * DD + tn * 8];
            float4 cb0 = *(float4*)&cy_s[xx0 * DD + tn * 8 + 4];
            float4 cb1 = *(float4*)&cy_s[xx1 * DD + tn * 8 + 4];
            float2 p0 = unpack2(acc[m][0]);
            float2 p1 = unpack2(acc[m][1]);
            float2 p2 = unpack2(acc[m][2]);
            float2 p3 = unpack2(acc[m][3]);
            oa.x = p0.x + b2a.x + fmaf(wx, ca1.x - ca0.x, ca0.x);
            oa.y = p0.y + b2a.y + fmaf(wx, ca1.y - ca0.y, ca0.y);
            oa.z = p1.x + b2a.z + fmaf(wx, ca1.z - ca0.z, ca0.z);
            oa.w = p1.y + b2a.w + fmaf(wx, ca1.w - ca0.w, ca0.w);
            ob.x = p2.x + b2b.x + fmaf(wx, cb1.x - cb0.x, cb0.x);
            ob.y = p2.y + b2b.y + fmaf(wx, cb1.y - cb0.y, cb0.y);
            ob.z = p3.x + b2b.z + fmaf(wx, cb1.z - cb0.z, cb0.z);
            ob.w = p3.y + b2b.w + fmaf(wx, cb1.w - cb0.w, cb0.w);
        }
        stcs4(&orow[x * DD + tn * 8],     oa);
        stcs4(&orow[x * DD + tn * 8 + 4], ob);
    }

    if (write_mask && tid < MW)
        mrow[tid] = (tid < Ws) ? 1.f : 0.f;
}

extern "C" void kernel_launch(void* const* d_in, const int* in_sizes, int n_in,
                              void* d_out, int out_size)
{
    const float* canon = (const float*)d_in[0];   // [8][8][512]
    const float* w1    = (const float*)d_in[1];   // [2][64]
    const float* b1    = (const float*)d_in[2];   // [64]
    const float* w2    = (const float*)d_in[3];   // [64][512]
    const float* b2    = (const float*)d_in[4];   // [512]
    const int*   hl    = (const int*)d_in[6];     // target_h_list [64]
    const int*   wl    = (const int*)d_in[7];     // target_w_list [64]
    float* out = (float*)d_out;

    long long q = (long long)BB * MH * MW * DD;
    int write_mask = ((long long)out_size > q) ? 1 : 0;

    k_main<<<dim3(MH, BB), 256>>>(canon, w1, b1, w2, b2, hl, wl, out,
                                  write_mask);
}